// round 1
// baseline (speedup 1.0000x reference)
#include <cuda_runtime.h>
#include <cstdint>

#define TSTEPS 2048
#define BATCH  128
#define HID    256
#define INDIM  82
#define CLU    8
#define BPC    8      // batches per cluster
#define NTHR   256

// ---- shared memory layout (bytes) ----
#define OFF_W4    0
#define SZ_W4     (64*128*16)            // W_hh slice as float4 [k4][row]  = 131072
#define OFF_WIH   (OFF_W4 + SZ_W4)       // 131072
#define SZ_WIH    (128*INDIM*4)          // 41984
#define OFF_BIAS  (OFF_WIH + SZ_WIH)     // 173056
#define SZ_BIAS   (128*4)
#define OFF_HBUF  (OFF_BIAS + SZ_BIAS)   // 173568 ; double-buffered h [2][8][256]
#define SZ_HBUF   (2*BPC*HID*4)          // 16384
#define OFF_GATES (OFF_HBUF + SZ_HBUF)   // 189952 ; gates [128][9] padded
#define SZ_GATES  (128*9*4)              // 4608
#define OFF_INP   (OFF_GATES + SZ_GATES) // 194560 ; per-step x/a/r/d for 8 batches
#define SZ_INP    (128)
#define SMEM_TOTAL (OFF_INP + SZ_INP)    // 194688

typedef unsigned long long ull;

__device__ __forceinline__ ull fma2(ull a, ull b, ull c){
  ull d; asm("fma.rn.f32x2 %0, %1, %2, %3;" : "=l"(d) : "l"(a),"l"(b),"l"(c)); return d;
}
__device__ __forceinline__ float lo32(ull v){ return __uint_as_float((unsigned)(v & 0xffffffffull)); }
__device__ __forceinline__ float hi32(ull v){ return __uint_as_float((unsigned)(v >> 32)); }
__device__ __forceinline__ float sigf(float x){ return __fdividef(1.f, 1.f + __expf(-x)); }
__device__ __forceinline__ float tanhf_(float x){ return __fdividef(2.f, 1.f + __expf(-2.f*x)) - 1.f; }
__device__ __forceinline__ uint32_t s2u(const void* p){
  uint32_t a;
  asm("{.reg .u64 t; cvta.to.shared.u64 t, %1; cvt.u32.u64 %0, t;}" : "=r"(a) : "l"(p));
  return a;
}

extern __shared__ char smem[];

__global__ void __cluster_dims__(CLU,1,1) __launch_bounds__(NTHR,1)
lstm_scan_kernel(const int* __restrict__ X, const float* __restrict__ H0,
                 const int* __restrict__ A, const float* __restrict__ R,
                 const float* __restrict__ Dn,
                 const float* __restrict__ Wih, const float* __restrict__ Whh,
                 const float* __restrict__ bih, const float* __restrict__ bhh,
                 float* __restrict__ out)
{
  const int tid = threadIdx.x;
  const int uc  = blockIdx.x & (CLU-1);   // cluster rank: which 32 hidden units
  const int bg  = blockIdx.x / CLU;       // which batch group of 8
  const int gb0 = bg * BPC;

  float4* W4s    = (float4*)(smem + OFF_W4);
  float*  WihS   = (float*)(smem + OFF_WIH);
  float*  biasS  = (float*)(smem + OFF_BIAS);
  float*  hbuf   = (float*)(smem + OFF_HBUF);
  float*  gatesS = (float*)(smem + OFF_GATES);
  int*    xs  = (int*)(smem + OFF_INP);
  int*    as_ = xs + 8;
  float*  rs  = (float*)(as_ + 8);
  float*  ds  = rs + 8;

  // ---- one-time weight staging ----
  // local row lr in [0,128): gate = lr/32 (i,f,g,o), unit = uc*32 + lr%32
  for (int i = tid; i < 64*128; i += NTHR){
    int k4 = i >> 7, lr = i & 127;
    int gr = ((lr >> 5) << 8) + uc*32 + (lr & 31);
    W4s[(k4 << 7) + lr] = ((const float4*)Whh)[gr*64 + k4];
  }
  for (int i = tid; i < 128*INDIM; i += NTHR){
    int lr = i / INDIM, c0 = i - lr*INDIM;
    int gr = ((lr >> 5) << 8) + uc*32 + (lr & 31);
    WihS[i] = Wih[gr*INDIM + c0];
  }
  for (int i = tid; i < 128; i += NTHR){
    int gr = ((i >> 5) << 8) + uc*32 + (i & 31);
    biasS[i] = bih[gr] + bhh[gr];
  }
  // initial h (full 256-vector for our 8 batches)
  for (int i = tid; i < BPC*HID; i += NTHR){
    int b = i >> 8, k = i & 255;
    hbuf[i] = H0[(gb0 + b)*(2*HID) + k];
  }
  // epilogue thread identity: one (batch, unit) pair per thread
  const int eb = tid >> 5, eu = tid & 31;
  const int ug = uc*32 + eu;
  const int gbb = gb0 + eb;
  float c = H0[gbb*(2*HID) + HID + ug];
  float h_last = 0.f;

  __syncthreads();

  // GEMM mapping: 8 warps; warps 0-3 -> batches 0-3, warps 4-7 -> batches 4-7
  // warp covers rows rowbase..rowbase+31 via 4 row-groups of 8
  const int w = tid >> 5, lane = tid & 31;
  const int b0 = (w >> 2) * 4;
  const int rowbase = (w & 3) * 32;
  const int r = lane >> 2, bl = lane & 3;
  const int myb = b0 + bl;
  const int row0 = rowbase + r;

  const uint32_t sb = s2u(smem);
  int cur = 0;

  for (int t = 0; t < TSTEPS; ++t){
    // prefetch this step's scalar inputs (consumed after the __syncthreads below)
    if (tid < 32){
      int b = tid & 7, wch = tid >> 3;
      long idx = (long)(gb0 + b)*TSTEPS + t;
      if      (wch == 0) xs[b]  = X[idx];
      else if (wch == 1) as_[b] = A[idx];
      else if (wch == 2) rs[b]  = R[idx];
      else               ds[b]  = Dn[idx];
    }

    // ---- recurrent GEMM: mv[row][b] = sum_k W[row][k] * h[b][k] (f32x2 packed) ----
    const ulonglong2* hp = (const ulonglong2*)(hbuf + cur*(BPC*HID) + myb*HID);
    const ulonglong2* wp = (const ulonglong2*)W4s + row0;
    ull a0=0, a1=0, a2=0, a3=0;
    #pragma unroll 8
    for (int k4 = 0; k4 < 64; ++k4){
      ulonglong2 hv  = hp[k4];       // broadcast within warp (4 distinct addrs)
      ulonglong2 w0v = wp[0];        // 8 distinct addrs, 4-lane multicast each
      ulonglong2 w1v = wp[8];
      ulonglong2 w2v = wp[16];
      ulonglong2 w3v = wp[24];
      wp += 128;
      a0 = fma2(w0v.x, hv.x, a0); a0 = fma2(w0v.y, hv.y, a0);
      a1 = fma2(w1v.x, hv.x, a1); a1 = fma2(w1v.y, hv.y, a1);
      a2 = fma2(w2v.x, hv.x, a2); a2 = fma2(w2v.y, hv.y, a2);
      a3 = fma2(w3v.x, hv.x, a3); a3 = fma2(w3v.y, hv.y, a3);
    }
    gatesS[(row0     )*9 + myb] = lo32(a0) + hi32(a0);
    gatesS[(row0 +  8)*9 + myb] = lo32(a1) + hi32(a1);
    gatesS[(row0 + 16)*9 + myb] = lo32(a2) + hi32(a2);
    gatesS[(row0 + 24)*9 + myb] = lo32(a3) + hi32(a3);

    __syncthreads();

    // ---- epilogue: x_proj gather + LSTM cell for this thread's (batch,unit) ----
    int   xi = xs[eb], ai = as_[eb];
    float rv = rs[eb], dv = ds[eb];
    float gate[4];
    #pragma unroll
    for (int g4 = 0; g4 < 4; ++g4){
      int lr = g4*32 + eu;
      const float* wr = WihS + lr*INDIM;
      float xp = wr[xi] + wr[64 + ai] + wr[80]*rv + wr[81]*dv + biasS[lr];
      gate[g4] = gatesS[lr*9 + eb] + xp;
    }
    float I = sigf(gate[0]);
    float F = sigf(gate[1]);
    float G = tanhf_(gate[2]);
    float O = sigf(gate[3]);
    c = F*c + I*G;
    float hv = O * tanhf_(c);
    h_last = hv;

    // features[b][t][u]
    out[((size_t)gbb*TSTEPS + t)*HID + ug] = hv;

    // broadcast h to every CTA's next-phase h buffer (incl. self) via DSMEM
    uint32_t la = sb + OFF_HBUF + (unsigned)(((cur^1)*(BPC*HID) + eb*HID + ug)*4);
    #pragma unroll
    for (int p = 0; p < CLU; ++p){
      uint32_t ra;
      asm volatile("mapa.shared::cluster.u32 %0, %1, %2;" : "=r"(ra) : "r"(la), "r"(p));
      asm volatile("st.shared::cluster.f32 [%0], %1;" :: "r"(ra), "f"(hv) : "memory");
    }

    asm volatile("barrier.cluster.arrive.aligned;" ::: "memory");
    asm volatile("barrier.cluster.wait.aligned;"   ::: "memory");
    cur ^= 1;
  }

  // final_hidden = [hT | cT], starts after features
  size_t fo = (size_t)BATCH*TSTEPS*HID;
  out[fo + (size_t)gbb*(2*HID) + ug]       = h_last;
  out[fo + (size_t)gbb*(2*HID) + HID + ug] = c;
}

extern "C" void kernel_launch(void* const* d_in, const int* in_sizes, int n_in,
                              void* d_out, int out_size)
{
  const int*   X   = (const int*)  d_in[0];
  const float* H0  = (const float*)d_in[1];
  const int*   A   = (const int*)  d_in[2];
  const float* R   = (const float*)d_in[3];
  const float* Dn  = (const float*)d_in[4];
  const float* Wih = (const float*)d_in[5];
  const float* Whh = (const float*)d_in[6];
  const float* bih = (const float*)d_in[7];
  const float* bhh = (const float*)d_in[8];
  float* out = (float*)d_out;

  cudaFuncSetAttribute(lstm_scan_kernel,
                       cudaFuncAttributeMaxDynamicSharedMemorySize, SMEM_TOTAL);
  lstm_scan_kernel<<<BATCH, NTHR, SMEM_TOTAL>>>(X, H0, A, R, Dn, Wih, Whh, bih, bhh, out);
}

// round 2
// speedup vs baseline: 1.4908x; 1.4908x over previous
#include <cuda_runtime.h>
#include <cstdint>

#define TSTEPS 2048
#define BATCH  128
#define HID    256
#define INDIM  82
#define CLU    8
#define BPC    8
#define NTHR   512
#define HSTRIDE 264   // padded h row (floats) -> conflict-free batch banks

// ---- shared memory layout (bytes) ----
#define OFF_W4    0
#define SZ_W4     (64*128*16)             // W_hh slice float4 [k4][row] = 131072
#define OFF_WIH   (OFF_W4 + SZ_W4)        // 131072
#define SZ_WIH    (128*INDIM*4)           // 41984
#define OFF_BIAS  (OFF_WIH + SZ_WIH)      // 173056
#define SZ_BIAS   (512)
#define OFF_HBUF  (OFF_BIAS + SZ_BIAS)    // 173568 ; [2][8][HSTRIDE] floats
#define SZ_HBUF   (2*BPC*HSTRIDE*4)       // 16896
#define OFF_GATES (OFF_HBUF + SZ_HBUF)    // 190464 ; [2][128][9] floats
#define SZ_GATES  (2*128*9*4)             // 9216
#define OFF_INP   (OFF_GATES + SZ_GATES)  // 199680 ; [2] x (x,a int8 r,d f8) = 256B
#define SZ_INP    (2*128)
#define OFF_MBAR  (OFF_INP + SZ_INP)      // 199936 (8B aligned)
#define SMEM_TOTAL (OFF_MBAR + 16)        // 199952

#define EXCH_BYTES (CLU*BPC*32*4)         // 8192 bytes per phase per CTA

typedef unsigned long long ull;

__device__ __forceinline__ ull fma2(ull a, ull b, ull c){
  ull d; asm("fma.rn.f32x2 %0, %1, %2, %3;" : "=l"(d) : "l"(a),"l"(b),"l"(c)); return d;
}
__device__ __forceinline__ float lo32(ull v){ return __uint_as_float((unsigned)(v & 0xffffffffull)); }
__device__ __forceinline__ float hi32(ull v){ return __uint_as_float((unsigned)(v >> 32)); }
__device__ __forceinline__ float sigf(float x){ return __fdividef(1.f, 1.f + __expf(-x)); }
__device__ __forceinline__ float tanhf_(float x){ return __fdividef(2.f, 1.f + __expf(-2.f*x)) - 1.f; }
__device__ __forceinline__ uint32_t s2u(const void* p){
  uint32_t a;
  asm("{.reg .u64 t; cvta.to.shared.u64 t, %1; cvt.u32.u64 %0, t;}" : "=r"(a) : "l"(p));
  return a;
}
__device__ __forceinline__ void mbar_init(uint32_t m, int cnt){
  asm volatile("mbarrier.init.shared.b64 [%0], %1;" :: "r"(m), "r"(cnt) : "memory");
}
__device__ __forceinline__ void mbar_arm(uint32_t m, int bytes){
  asm volatile("mbarrier.arrive.expect_tx.shared.b64 _, [%0], %1;" :: "r"(m), "r"(bytes) : "memory");
}
__device__ __forceinline__ void mbar_wait(uint32_t m, uint32_t parity){
  asm volatile(
    "{\n\t.reg .pred P;\n\t"
    "WLP%=:\n\t"
    "mbarrier.try_wait.parity.acquire.cluster.shared::cta.b64 P, [%0], %1, 0x989680;\n\t"
    "@!P bra WLP%=;\n\t}"
    :: "r"(m), "r"(parity) : "memory");
}
__device__ __forceinline__ void st_async_f32(uint32_t raddr, float v, uint32_t rmbar){
  asm volatile("st.async.shared::cluster.mbarrier::complete_tx::bytes.b32 [%0], %1, [%2];"
               :: "r"(raddr), "r"(__float_as_uint(v)), "r"(rmbar) : "memory");
}
__device__ __forceinline__ uint32_t mapa_u32(uint32_t la, int rank){
  uint32_t ra;
  asm("mapa.shared::cluster.u32 %0, %1, %2;" : "=r"(ra) : "r"(la), "r"(rank));
  return ra;
}

extern __shared__ char smem[];

__global__ void __cluster_dims__(CLU,1,1) __launch_bounds__(NTHR,1)
lstm_scan_kernel(const int* __restrict__ X, const float* __restrict__ H0,
                 const int* __restrict__ A, const float* __restrict__ R,
                 const float* __restrict__ Dn,
                 const float* __restrict__ Wih, const float* __restrict__ Whh,
                 const float* __restrict__ bih, const float* __restrict__ bhh,
                 float* __restrict__ out)
{
  const int tid = threadIdx.x;
  const int uc  = blockIdx.x & (CLU-1);   // cluster rank: which 32 hidden units
  const int bg  = blockIdx.x / CLU;       // batch group of 8
  const int gb0 = bg * BPC;

  float4* W4s    = (float4*)(smem + OFF_W4);
  float*  WihS   = (float*)(smem + OFF_WIH);
  float*  biasS  = (float*)(smem + OFF_BIAS);
  float*  hbuf   = (float*)(smem + OFF_HBUF);
  float*  gatesS = (float*)(smem + OFF_GATES);

  const uint32_t sb = s2u(smem);

  // ---- one-time staging ----
  // local row lr in [0,128): gate = lr/32, unit = uc*32 + lr%32
  for (int i = tid; i < 64*128; i += NTHR){
    int k4 = i >> 7, lr = i & 127;
    int gr = ((lr >> 5) << 8) + uc*32 + (lr & 31);
    W4s[(k4 << 7) + lr] = ((const float4*)Whh)[gr*64 + k4];
  }
  for (int i = tid; i < 128*INDIM; i += NTHR){
    int lr = i / INDIM, c0 = i - lr*INDIM;
    int gr = ((lr >> 5) << 8) + uc*32 + (lr & 31);
    WihS[i] = Wih[gr*INDIM + c0];
  }
  for (int i = tid; i < 128; i += NTHR){
    int gr = ((i >> 5) << 8) + uc*32 + (i & 31);
    biasS[i] = bih[gr] + bhh[gr];
  }
  // initial h for our 8 batches -> buffer 0
  for (int i = tid; i < BPC*HID; i += NTHR){
    int b = i >> 8, k = i & 255;
    hbuf[b*HSTRIDE + k] = H0[(gb0 + b)*(2*HID) + k];
  }

  if (tid == 0){
    mbar_init(sb + OFF_MBAR,     1);
    mbar_init(sb + OFF_MBAR + 8, 1);
    mbar_arm (sb + OFF_MBAR,     EXCH_BYTES);   // covers step-2 data
    mbar_arm (sb + OFF_MBAR + 8, EXCH_BYTES);   // covers step-1 data
  }
  __syncthreads();
  asm volatile("barrier.cluster.arrive.aligned;" ::: "memory");
  asm volatile("barrier.cluster.wait.aligned;"   ::: "memory");

  // GEMM mapping: 16 warps. warp w: batches (w&1)*4 .. +3 via bl, rows rowsec*16 + {r, r+8}
  const int w = tid >> 5, lane = tid & 31;
  const int b0 = (w & 1) * 4;
  const int rowsec = w >> 1;
  const int r = lane >> 2, bl = lane & 3;
  const int myb = b0 + bl;
  const int row0 = rowsec*16 + r;

  // epilogue identity (threads 0..255): one (batch, unit)
  const int eb = tid >> 5, eu = tid & 31;   // valid when tid<256 (eb<8)
  const int ug = uc*32 + eu;
  const int gbb = gb0 + (eb & 7);
  float c = (tid < 256) ? H0[gbb*(2*HID) + HID + ug] : 0.f;
  float h_last = 0.f;

  uint32_t ph0 = 0, ph1 = 0;

  for (int t = 0; t < TSTEPS; ++t){
    const int cb = t & 1;          // current h / gates / input buffer
    const int nb = cb ^ 1;

    if (t > 0){
      uint32_t m = sb + OFF_MBAR + cb*8;
      uint32_t par = cb ? ph1 : ph0;
      mbar_wait(m, par);
      if (cb) ph1 ^= 1; else ph0 ^= 1;
      if (tid == 0) mbar_arm(m, EXCH_BYTES);   // re-arm for step t+2
    }

    // prefetch this step's scalar inputs into buffer cb
    if (tid < 32){
      int b = tid & 7, wch = tid >> 3;
      long idx = (long)(gb0 + b)*TSTEPS + t;
      char* inp = smem + OFF_INP + cb*128;
      if      (wch == 0) ((int*)inp)[b]        = X[idx];
      else if (wch == 1) ((int*)inp)[8 + b]    = A[idx];
      else if (wch == 2) ((float*)inp)[16 + b] = R[idx];
      else               ((float*)inp)[24 + b] = Dn[idx];
    }

    // ---- recurrent GEMM: gates[row][b] = sum_k W[row][k]*h[b][k] ----
    {
      const ulonglong2* hp = (const ulonglong2*)(hbuf + cb*(BPC*HSTRIDE) + myb*HSTRIDE);
      const ulonglong2* wp = (const ulonglong2*)W4s + row0;
      ull a0 = 0, a1 = 0;
      #pragma unroll 8
      for (int k4 = 0; k4 < 64; ++k4){
        ulonglong2 hv = hp[k4];      // 4 distinct addrs/warp, conflict-free (HSTRIDE pad)
        ulonglong2 w0 = wp[0];       // 8 distinct contiguous float4 -> 128B, 4-lane multicast
        ulonglong2 w1 = wp[8];
        wp += 128;
        a0 = fma2(w0.x, hv.x, a0); a0 = fma2(w0.y, hv.y, a0);
        a1 = fma2(w1.x, hv.x, a1); a1 = fma2(w1.y, hv.y, a1);
      }
      float* gG = gatesS + cb*(128*9);
      gG[(row0    )*9 + myb] = lo32(a0) + hi32(a0);
      gG[(row0 + 8)*9 + myb] = lo32(a1) + hi32(a1);
    }

    __syncthreads();

    // ---- epilogue on threads 0..255 ----
    if (tid < 256){
      const char* inp = smem + OFF_INP + cb*128;
      int   xi = ((const int*)inp)[eb];
      int   ai = ((const int*)inp)[8 + eb];
      float rv = ((const float*)inp)[16 + eb];
      float dv = ((const float*)inp)[24 + eb];
      const float* gG = gatesS + cb*(128*9);

      float gate[4];
      #pragma unroll
      for (int g4 = 0; g4 < 4; ++g4){
        int lr = g4*32 + eu;
        const float* wr = WihS + lr*INDIM;
        float xp = wr[xi] + wr[64 + ai] + wr[80]*rv + wr[81]*dv + biasS[lr];
        gate[g4] = gG[lr*9 + eb] + xp;
      }
      float I = sigf(gate[0]);
      float F = sigf(gate[1]);
      float G = tanhf_(gate[2]);
      float O = sigf(gate[3]);
      c = F*c + I*G;
      float hv = O * tanhf_(c);
      h_last = hv;

      // broadcast h (for step t+1) to all 8 CTAs' buffer nb, completing their mbar[nb]
      if (t < TSTEPS-1){
        uint32_t la = sb + OFF_HBUF + 4u*(unsigned)(nb*(BPC*HSTRIDE) + eb*HSTRIDE + ug);
        uint32_t lm = sb + OFF_MBAR + nb*8;
        #pragma unroll
        for (int p = 0; p < CLU; ++p){
          st_async_f32(mapa_u32(la, p), hv, mapa_u32(lm, p));
        }
      }

      // features[b][t][u]
      out[((size_t)gbb*TSTEPS + t)*HID + ug] = hv;
    }
  }

  if (tid < 256){
    size_t fo = (size_t)BATCH*TSTEPS*HID;
    out[fo + (size_t)gbb*(2*HID) + ug]       = h_last;
    out[fo + (size_t)gbb*(2*HID) + HID + ug] = c;
  }

  asm volatile("barrier.cluster.arrive.aligned;" ::: "memory");
  asm volatile("barrier.cluster.wait.aligned;"   ::: "memory");
}

extern "C" void kernel_launch(void* const* d_in, const int* in_sizes, int n_in,
                              void* d_out, int out_size)
{
  const int*   X   = (const int*)  d_in[0];
  const float* H0  = (const float*)d_in[1];
  const int*   A   = (const int*)  d_in[2];
  const float* R   = (const float*)d_in[3];
  const float* Dn  = (const float*)d_in[4];
  const float* Wih = (const float*)d_in[5];
  const float* Whh = (const float*)d_in[6];
  const float* bih = (const float*)d_in[7];
  const float* bhh = (const float*)d_in[8];
  float* out = (float*)d_out;

  cudaFuncSetAttribute(lstm_scan_kernel,
                       cudaFuncAttributeMaxDynamicSharedMemorySize, SMEM_TOTAL);
  lstm_scan_kernel<<<BATCH, NTHR, SMEM_TOTAL>>>(X, H0, A, R, Dn, Wih, Whh, bih, bhh, out);
}